// round 6
// baseline (speedup 1.0000x reference)
#include <cuda_runtime.h>

// Fixed problem shapes
#define T_STEPS 5
#define BS      32
#define C       64
#define H       64
#define W       64
#define VTH     1.0f
// gamma = DROP_RATE / BLOCK_SIZE^2 = 0.1 / 49
#define GAMMA   0.002040816326530612f

#define N_PLANES (T_STEPS * BS)               // 160
#define PLANE    (H * W)                      // 4096
#define PLANE4   (PLANE / 4)                  // 1024
#define ELEMS_PER_T (BS * C * H * W)          // 8388608
#define VEC_PER_T   (ELEMS_PER_T / 4)         // 2097152

#define MAX_SEEDS 1024                        // hard cap (E[k] ~ 8.4/plane)

// dropblock keep-mask scratch: [160, 64, 64] float (2.62 MB), static device mem
__device__ __align__(16) float d_bm[N_PLANES * PLANE];

// ---------------------------------------------------------------------------
// Kernel 1: sparse-seed block mask. One 256-thread block per plane.
// Seeds (mr < gamma) ~8.4 per 64x64 plane: gather coords into a tiny smem
// list, then keep = !(exists seed with Chebyshev dist <= 3). float4 I/O.
// ---------------------------------------------------------------------------
__global__ void __launch_bounds__(256) block_mask_kernel(const float4* __restrict__ mr4) {
    __shared__ int s_cnt;
    __shared__ int s_pts[MAX_SEEDS];   // packed (r << 8) | w

    const int n   = blockIdx.x;
    const int tid = threadIdx.x;
    if (tid == 0) s_cnt = 0;
    __syncthreads();

    #pragma unroll
    for (int j = 0; j < 4; ++j) {
        const int idx = tid + j * 256;                 // 0..1023 float4 index
        const float4 v = mr4[n * PLANE4 + idx];
        const int r  = idx >> 4;
        const int w0 = (idx & 15) << 2;
        if (v.x < GAMMA) s_pts[atomicAdd(&s_cnt, 1)] = (r << 8) | (w0 + 0);
        if (v.y < GAMMA) s_pts[atomicAdd(&s_cnt, 1)] = (r << 8) | (w0 + 1);
        if (v.z < GAMMA) s_pts[atomicAdd(&s_cnt, 1)] = (r << 8) | (w0 + 2);
        if (v.w < GAMMA) s_pts[atomicAdd(&s_cnt, 1)] = (r << 8) | (w0 + 3);
    }
    __syncthreads();

    const int k = s_cnt;
    float4* __restrict__ bm4 = reinterpret_cast<float4*>(d_bm) + n * PLANE4;

    #pragma unroll
    for (int j = 0; j < 4; ++j) {
        const int idx = tid + j * 256;
        const int h   = idx >> 4;
        const int wb  = (idx & 15) << 2;
        float4 m = make_float4(1.f, 1.f, 1.f, 1.f);
        for (int i = 0; i < k; ++i) {
            const int p  = s_pts[i];
            const int pr = p >> 8;
            if (abs(pr - h) <= 3) {
                const int dw = (p & 255) - wb;
                if (dw >= -3 && dw <= 3) m.x = 0.f;
                if (dw >= -2 && dw <= 4) m.y = 0.f;
                if (dw >= -1 && dw <= 5) m.z = 0.f;
                if (dw >=  0 && dw <= 6) m.w = 0.f;
            }
        }
        bm4[idx] = m;
    }

    cudaTriggerProgrammaticLaunchCompletion();
}

// ---------------------------------------------------------------------------
// Kernel 2: LIF scan (exact R3 body — 46.3us, 78.1% DRAM). One float4 site per
// thread, u in registers, float4 bm loads from L2-hot d_bm. PDL-gated at top.
// ---------------------------------------------------------------------------
__global__ void __launch_bounds__(256) lif_kernel(const float4* __restrict__ x,
                                                  float4* __restrict__ out) {
    cudaGridDependencySynchronize();

    const int v = blockIdx.x * 256 + threadIdx.x;   // grid exactly covers VEC_PER_T

    const int wq = v & 15;
    const int h  = (v >> 4) & 63;
    const int b  = v >> 16;
    const int bm_base = ((b << 6) + h) * 16 + wq;
    const float4* __restrict__ bm4 = reinterpret_cast<const float4*>(d_bm);

    float4 u = make_float4(0.f, 0.f, 0.f, 0.f);

    #pragma unroll
    for (int t = 0; t < T_STEPS; ++t) {
        const float4 xt  = x[t * VEC_PER_T + v];
        const float4 bmt = bm4[(t * BS) * PLANE4 + bm_base];
        float4 o;

        u.x = (u.x > VTH) ? xt.x : fmaf(0.5f, u.x, xt.x);
        u.y = (u.y > VTH) ? xt.y : fmaf(0.5f, u.y, xt.y);
        u.z = (u.z > VTH) ? xt.z : fmaf(0.5f, u.z, xt.z);
        u.w = (u.w > VTH) ? xt.w : fmaf(0.5f, u.w, xt.w);

        o.x = (u.x > VTH) ? bmt.x : 0.0f;
        o.y = (u.y > VTH) ? bmt.y : 0.0f;
        o.z = (u.z > VTH) ? bmt.z : 0.0f;
        o.w = (u.w > VTH) ? bmt.w : 0.0f;

        out[t * VEC_PER_T + v] = o;
    }
}

extern "C" void kernel_launch(void* const* d_in, const int* in_sizes, int n_in,
                              void* d_out, int out_size) {
    const float4* x  = (const float4*)d_in[0];
    const float4* mr = (const float4*)d_in[1];
    float4* out      = (float4*)d_out;

    block_mask_kernel<<<N_PLANES, 256>>>(mr);

    // PDL launch: removes node gap / launch ramp; cudaGridDependencySynchronize()
    // at the top of lif gates d_bm consumption.
    cudaLaunchConfig_t cfg = {};
    cfg.gridDim  = dim3(VEC_PER_T / 256);
    cfg.blockDim = dim3(256);
    cfg.stream   = 0;
    cudaLaunchAttribute attr[1];
    attr[0].id = cudaLaunchAttributeProgrammaticStreamSerialization;
    attr[0].val.programmaticStreamSerializationAllowed = 1;
    cfg.attrs    = attr;
    cfg.numAttrs = 1;
    cudaLaunchKernelEx(&cfg, lif_kernel, x, out);
}